// round 6
// baseline (speedup 1.0000x reference)
#include <cuda_runtime.h>

// Depthwise 3x3 (center tap zero) + residual, NHWC x[32,56,56,256] fp32.
// R3 structure (batch-of-4 sliding window, 12 batched loads) was best at
// 37.6us / DRAM 64.5% / occ 35%. R5 showed prefetch-regs spill (128 regs).
// R6: SAME structure at scalar-float granularity -> window 18 regs + taps 8
// -> fits 5 CTAs/SM (62.5% occ cap) via __launch_bounds__(256,5). Warp
// memory wavefronts unchanged (LDG.32 warp = 1 sector line); only warp
// instruction count rises, which has headroom (issue was 26%).

#define Bn 32
#define Hn 56
#define Wn 56
#define Cn 256

__global__ __launch_bounds__(256, 5)
void contour_integration_kernel(const float* __restrict__ x,
                                const float* __restrict__ k,
                                float* __restrict__ out)
{
    const int c  = threadIdx.x;        // 0..255 channel
    const int bh = blockIdx.x;         // 0..B*H-1
    const int h  = bh % Hn;

    // taps (cross-correlation; center k[1][1] excluded)
    float k00 = __ldg(&k[0 * Cn + c]);
    float k01 = __ldg(&k[1 * Cn + c]);
    float k02 = __ldg(&k[2 * Cn + c]);
    float k10 = __ldg(&k[3 * Cn + c]);
    float k12 = __ldg(&k[5 * Cn + c]);
    float k20 = __ldg(&k[6 * Cn + c]);
    float k21 = __ldg(&k[7 * Cn + c]);
    float k22 = __ldg(&k[8 * Cn + c]);

    // boundary rows: zero taps + clamp pointers -> all row loads unconditional
    const bool hm = (h > 0);
    const bool hp = (h < Hn - 1);
    if (!hm) { k00 = 0.f; k01 = 0.f; k02 = 0.f; }
    if (!hp) { k20 = 0.f; k21 = 0.f; k22 = 0.f; }

    const int base = bh * Wn * Cn + c;             // max ~25.7M, 32-bit safe
    const float* __restrict__ row1 = x + base;
    const float* __restrict__ row0 = hm ? (row1 - Wn * Cn) : row1;
    const float* __restrict__ row2 = hp ? (row1 + Wn * Cn) : row1;
    float* __restrict__ orow = out + base;

    // window: win[row][p], p=0..5 = columns w-1 .. w+4 for batch start w
    float win[3][6];

    win[0][0] = 0.f; win[1][0] = 0.f; win[2][0] = 0.f;   // col -1
    #pragma unroll
    for (int p = 1; p <= 5; ++p) {
        const int wc = p - 1;
        win[0][p] = __ldg(&row0[wc * Cn]);
        win[1][p] = __ldg(&row1[wc * Cn]);
        win[2][p] = __ldg(&row2[wc * Cn]);
    }

    #pragma unroll
    for (int bidx = 0; bidx < 14; ++bidx) {
        const int w = bidx * 4;

        // compute 4 outputs w..w+3 (output w+j uses window positions j..j+2)
        #pragma unroll
        for (int j = 0; j < 4; ++j) {
            float acc = win[1][j + 1];             // residual (center x)
            acc = fmaf(k00, win[0][j],     acc);
            acc = fmaf(k01, win[0][j + 1], acc);
            acc = fmaf(k02, win[0][j + 2], acc);
            acc = fmaf(k10, win[1][j],     acc);
            acc = fmaf(k12, win[1][j + 2], acc);
            acc = fmaf(k20, win[2][j],     acc);
            acc = fmaf(k21, win[2][j + 1], acc);
            acc = fmaf(k22, win[2][j + 2], acc);
            orow[(w + j) * Cn] = acc;
        }

        // shift window and batch-load the next 4 columns (12 independent LDGs)
        if (bidx < 13) {
            win[0][0] = win[0][4]; win[1][0] = win[1][4]; win[2][0] = win[2][4];
            win[0][1] = win[0][5]; win[1][1] = win[1][5]; win[2][1] = win[2][5];
            #pragma unroll
            for (int j = 0; j < 4; ++j) {
                const int wc = w + 5 + j;          // compile-time constant
                if (wc < Wn) {
                    win[0][2 + j] = __ldg(&row0[wc * Cn]);
                    win[1][2 + j] = __ldg(&row1[wc * Cn]);
                    win[2][2 + j] = __ldg(&row2[wc * Cn]);
                } else {
                    win[0][2 + j] = 0.f;
                    win[1][2 + j] = 0.f;
                    win[2][2 + j] = 0.f;
                }
            }
        }
    }
}

extern "C" void kernel_launch(void* const* d_in, const int* in_sizes, int n_in,
                              void* d_out, int out_size)
{
    const float* x = (const float*)d_in[0];   // [32,56,56,256] fp32
    const float* k = (const float*)d_in[1];   // [3,3,256] fp32
    float* out = (float*)d_out;

    dim3 block(Cn);             // 256 threads: one full (b,h) row, all channels
    dim3 grid(Bn * Hn);         // 1792 blocks
    contour_integration_kernel<<<grid, block>>>(x, k, out);
}

// round 9
// speedup vs baseline: 1.1091x; 1.1091x over previous
#include <cuda_runtime.h>

// Depthwise 3x3 (center tap zero) + residual, NHWC x[32,56,56,256] fp32.
// Lesson R3..R6: perf ~ bytes-in-flight/SM = warps x batched_loads x
// bytes-per-warp-load. R3 (float2, batch-4, 3 CTA, 80 regs) = best 37.6us.
// R6 (scalar, 5 CTA) halved bytes/warp-load -> slower. R7 = R3 structure
// EXACTLY, squeezed to 64 regs for 4 CTAs/SM: int row offsets instead of
// extra 64-bit pointers, out derived from one base. 12 x 256B loads/warp
// x ~32 warps/SM ~= 92KB in flight (+37% vs R3).

#define Bn 32
#define Hn 56
#define Wn 56
#define C2 128   // 256 channels / 2 per float2

__device__ __forceinline__ float2 f2fma(float2 k, float2 v, float2 a) {
    a.x = fmaf(k.x, v.x, a.x);
    a.y = fmaf(k.y, v.y, a.y);
    return a;
}

__global__ __launch_bounds__(256, 4)
void contour_integration_kernel(const float2* __restrict__ x,
                                const float2* __restrict__ k,
                                float2* __restrict__ out)
{
    const int c2 = threadIdx.x;                    // 0..127 channel pair
    const int bh = blockIdx.x * 2 + threadIdx.y;   // 0..B*H-1
    const int h  = bh % Hn;

    const float2 Z = make_float2(0.f, 0.f);

    // taps (cross-correlation; center k[1][1] excluded)
    float2 k00 = __ldg(&k[0 * C2 + c2]);
    float2 k01 = __ldg(&k[1 * C2 + c2]);
    float2 k02 = __ldg(&k[2 * C2 + c2]);
    float2 k10 = __ldg(&k[3 * C2 + c2]);
    float2 k12 = __ldg(&k[5 * C2 + c2]);
    float2 k20 = __ldg(&k[6 * C2 + c2]);
    float2 k21 = __ldg(&k[7 * C2 + c2]);
    float2 k22 = __ldg(&k[8 * C2 + c2]);

    // boundary rows: zero taps + clamped offsets -> all loads unconditional
    const bool hm = (h > 0);
    const bool hp = (h < Hn - 1);
    if (!hm) { k00 = Z; k01 = Z; k02 = Z; }
    if (!hp) { k20 = Z; k21 = Z; k22 = Z; }

    const int base = bh * Wn * C2 + c2;            // 32-bit safe (12.8M max)
    const float2* __restrict__ row1 = x + base;
    const int off0 = hm ? -(Wn * C2) : 0;          // int offset, 1 reg
    const int off2 = hp ?  (Wn * C2) : 0;          // int offset, 1 reg
    float2* __restrict__ orow = out + base;

    // window: win[row][p], p=0..5 = columns w-1 .. w+4 for batch start w
    float2 win[3][6];

    win[0][0] = Z; win[1][0] = Z; win[2][0] = Z;   // col -1
    #pragma unroll
    for (int p = 1; p <= 5; ++p) {
        const int wc = (p - 1) * C2;
        win[0][p] = __ldg(&row1[wc + off0]);
        win[1][p] = __ldg(&row1[wc]);
        win[2][p] = __ldg(&row1[wc + off2]);
    }

    #pragma unroll
    for (int bidx = 0; bidx < 14; ++bidx) {
        const int w = bidx * 4;

        // compute 4 outputs w..w+3 (output w+j uses window positions j..j+2)
        #pragma unroll
        for (int j = 0; j < 4; ++j) {
            float2 acc = win[1][j + 1];            // residual (center x)
            acc = f2fma(k00, win[0][j],     acc);
            acc = f2fma(k01, win[0][j + 1], acc);
            acc = f2fma(k02, win[0][j + 2], acc);
            acc = f2fma(k10, win[1][j],     acc);
            acc = f2fma(k12, win[1][j + 2], acc);
            acc = f2fma(k20, win[2][j],     acc);
            acc = f2fma(k21, win[2][j + 1], acc);
            acc = f2fma(k22, win[2][j + 2], acc);
            orow[(w + j) * C2] = acc;
        }

        // shift window, batch-load next 4 columns (12 independent LDG.64)
        if (bidx < 13) {
            win[0][0] = win[0][4]; win[1][0] = win[1][4]; win[2][0] = win[2][4];
            win[0][1] = win[0][5]; win[1][1] = win[1][5]; win[2][1] = win[2][5];
            #pragma unroll
            for (int j = 0; j < 4; ++j) {
                const int wc = (w + 5 + j) * C2;   // compile-time constant
                if (w + 5 + j < Wn) {
                    win[0][2 + j] = __ldg(&row1[wc + off0]);
                    win[1][2 + j] = __ldg(&row1[wc]);
                    win[2][2 + j] = __ldg(&row1[wc + off2]);
                } else {
                    win[0][2 + j] = Z;
                    win[1][2 + j] = Z;
                    win[2][2 + j] = Z;
                }
            }
        }
    }
}

extern "C" void kernel_launch(void* const* d_in, const int* in_sizes, int n_in,
                              void* d_out, int out_size)
{
    const float2* x = (const float2*)d_in[0];   // [32,56,56,256] fp32
    const float2* k = (const float2*)d_in[1];   // [3,3,256] fp32
    float2* out = (float2*)d_out;

    dim3 block(C2, 2);          // 256 threads: two full rows per block
    dim3 grid(Bn * Hn / 2);     // 896 blocks
    contour_integration_kernel<<<grid, block>>>(x, k, out);
}

// round 10
// speedup vs baseline: 1.2111x; 1.0919x over previous
#include <cuda_runtime.h>

// Depthwise 3x3 (center tap zero) + residual, NHWC x[32,56,56,256] fp32.
// Best so far: R3 (float2, batch-4 window, 80 regs, 3 CTA) = 37.6us,
// DRAM 64.5%, nothing saturated -> stall-structure bound. R10: rotating
// modulo-6 window, fully unrolled over W. After output w, its freed slot
// (w%6) is reloaded with column w+5 -> load->use distance = 4 outputs
// (~100 instr vs ~20 in R3), 12 loads in flight steady state, SAME
// register footprint as R3 (rotation = compile-time renaming, no MOVs,
// no per-iteration branches).

#define Bn 32
#define Hn 56
#define Wn 56
#define C2 128   // 256 channels / 2 per float2

__device__ __forceinline__ float2 f2fma(float2 k, float2 v, float2 a) {
    a.x = fmaf(k.x, v.x, a.x);
    a.y = fmaf(k.y, v.y, a.y);
    return a;
}

__global__ __launch_bounds__(256, 3)
void contour_integration_kernel(const float2* __restrict__ x,
                                const float2* __restrict__ k,
                                float2* __restrict__ out)
{
    const int c2 = threadIdx.x;                    // 0..127 channel pair
    const int bh = blockIdx.x * 2 + threadIdx.y;   // 0..B*H-1
    const int h  = bh % Hn;

    const float2 Z = make_float2(0.f, 0.f);

    // taps (cross-correlation; center k[1][1] excluded)
    float2 k00 = __ldg(&k[0 * C2 + c2]);
    float2 k01 = __ldg(&k[1 * C2 + c2]);
    float2 k02 = __ldg(&k[2 * C2 + c2]);
    float2 k10 = __ldg(&k[3 * C2 + c2]);
    float2 k12 = __ldg(&k[5 * C2 + c2]);
    float2 k20 = __ldg(&k[6 * C2 + c2]);
    float2 k21 = __ldg(&k[7 * C2 + c2]);
    float2 k22 = __ldg(&k[8 * C2 + c2]);

    // boundary rows: zero taps + clamped row pointers -> loads unconditional
    const bool hm = (h > 0);
    const bool hp = (h < Hn - 1);
    if (!hm) { k00 = Z; k01 = Z; k02 = Z; }
    if (!hp) { k20 = Z; k21 = Z; k22 = Z; }

    const int base = bh * Wn * C2 + c2;            // 32-bit safe
    const float2* __restrict__ row1 = x + base;
    const float2* __restrict__ row0 = hm ? (row1 - Wn * C2) : row1;
    const float2* __restrict__ row2 = hp ? (row1 + Wn * C2) : row1;
    float2* __restrict__ orow = out + base;

    // rotating window: slot(col) = (col + 1) % 6
    float2 win[3][6];

    // prologue: col -1 = Z (slot 0), cols 0..4 -> slots 1..5
    win[0][0] = Z; win[1][0] = Z; win[2][0] = Z;
    #pragma unroll
    for (int p = 1; p <= 5; ++p) {
        const int wc = (p - 1) * C2;
        win[0][p] = __ldg(&row0[wc]);
        win[1][p] = __ldg(&row1[wc]);
        win[2][p] = __ldg(&row2[wc]);
    }

    #pragma unroll
    for (int w = 0; w < Wn; ++w) {
        const int s0 = w % 6;          // col w-1
        const int s1 = (w + 1) % 6;    // col w
        const int s2 = (w + 2) % 6;    // col w+1

        float2 acc = win[1][s1];       // residual (center x)
        acc = f2fma(k00, win[0][s0], acc);
        acc = f2fma(k01, win[0][s1], acc);
        acc = f2fma(k02, win[0][s2], acc);
        acc = f2fma(k10, win[1][s0], acc);
        acc = f2fma(k12, win[1][s2], acc);
        acc = f2fma(k20, win[2][s0], acc);
        acc = f2fma(k21, win[2][s1], acc);
        acc = f2fma(k22, win[2][s2], acc);
        orow[w * C2] = acc;

        // slot s0 is now free: refill with column w+5 (first used at w+4)
        if (w < Wn - 5) {                          // compile-time (unrolled)
            const int wc = (w + 5) * C2;
            win[0][s0] = __ldg(&row0[wc]);
            win[1][s0] = __ldg(&row1[wc]);
            win[2][s0] = __ldg(&row2[wc]);
        } else if (w == Wn - 5) {
            // phantom col 56 (right edge) must read as zero at w = 55
            win[0][s0] = Z; win[1][s0] = Z; win[2][s0] = Z;
        }
    }
}

extern "C" void kernel_launch(void* const* d_in, const int* in_sizes, int n_in,
                              void* d_out, int out_size)
{
    const float2* x = (const float2*)d_in[0];   // [32,56,56,256] fp32
    const float2* k = (const float2*)d_in[1];   // [3,3,256] fp32
    float2* out = (float2*)d_out;

    dim3 block(C2, 2);          // 256 threads: two full rows per block
    dim3 grid(Bn * Hn / 2);     // 896 blocks
    contour_integration_kernel<<<grid, block>>>(x, k, out);
}

// round 14
// speedup vs baseline: 1.2310x; 1.0164x over previous
#include <cuda_runtime.h>

// Depthwise 3x3 (center tap zero) + residual, NHWC x[32,56,56,256] fp32.
// R10 (rotating window) == R3 == 37.6us, DRAM 65%: scheduling is exhausted;
// ~160MB DRAM traffic = 103MB writes + ~57MB read misses. R11 = R10 with
// streaming stores ONLY (__stcs): out lines become evict-first in L2 so
// they stop displacing x lines that h+-1 neighbor rows re-read -> fewer
// DRAM read misses. Everything else byte-identical to R10.

#define Bn 32
#define Hn 56
#define Wn 56
#define C2 128   // 256 channels / 2 per float2

__device__ __forceinline__ float2 f2fma(float2 k, float2 v, float2 a) {
    a.x = fmaf(k.x, v.x, a.x);
    a.y = fmaf(k.y, v.y, a.y);
    return a;
}

__global__ __launch_bounds__(256, 3)
void contour_integration_kernel(const float2* __restrict__ x,
                                const float2* __restrict__ k,
                                float2* __restrict__ out)
{
    const int c2 = threadIdx.x;                    // 0..127 channel pair
    const int bh = blockIdx.x * 2 + threadIdx.y;   // 0..B*H-1
    const int h  = bh % Hn;

    const float2 Z = make_float2(0.f, 0.f);

    // taps (cross-correlation; center k[1][1] excluded)
    float2 k00 = __ldg(&k[0 * C2 + c2]);
    float2 k01 = __ldg(&k[1 * C2 + c2]);
    float2 k02 = __ldg(&k[2 * C2 + c2]);
    float2 k10 = __ldg(&k[3 * C2 + c2]);
    float2 k12 = __ldg(&k[5 * C2 + c2]);
    float2 k20 = __ldg(&k[6 * C2 + c2]);
    float2 k21 = __ldg(&k[7 * C2 + c2]);
    float2 k22 = __ldg(&k[8 * C2 + c2]);

    // boundary rows: zero taps + clamped row pointers -> loads unconditional
    const bool hm = (h > 0);
    const bool hp = (h < Hn - 1);
    if (!hm) { k00 = Z; k01 = Z; k02 = Z; }
    if (!hp) { k20 = Z; k21 = Z; k22 = Z; }

    const int base = bh * Wn * C2 + c2;            // 32-bit safe
    const float2* __restrict__ row1 = x + base;
    const float2* __restrict__ row0 = hm ? (row1 - Wn * C2) : row1;
    const float2* __restrict__ row2 = hp ? (row1 + Wn * C2) : row1;
    float2* __restrict__ orow = out + base;

    // rotating window: slot(col) = (col + 1) % 6
    float2 win[3][6];

    // prologue: col -1 = Z (slot 0), cols 0..4 -> slots 1..5
    win[0][0] = Z; win[1][0] = Z; win[2][0] = Z;
    #pragma unroll
    for (int p = 1; p <= 5; ++p) {
        const int wc = (p - 1) * C2;
        win[0][p] = __ldg(&row0[wc]);
        win[1][p] = __ldg(&row1[wc]);
        win[2][p] = __ldg(&row2[wc]);
    }

    #pragma unroll
    for (int w = 0; w < Wn; ++w) {
        const int s0 = w % 6;          // col w-1
        const int s1 = (w + 1) % 6;    // col w
        const int s2 = (w + 2) % 6;    // col w+1

        float2 acc = win[1][s1];       // residual (center x)
        acc = f2fma(k00, win[0][s0], acc);
        acc = f2fma(k01, win[0][s1], acc);
        acc = f2fma(k02, win[0][s2], acc);
        acc = f2fma(k10, win[1][s0], acc);
        acc = f2fma(k12, win[1][s2], acc);
        acc = f2fma(k20, win[2][s0], acc);
        acc = f2fma(k21, win[2][s1], acc);
        acc = f2fma(k22, win[2][s2], acc);
        __stcs(&orow[w * C2], acc);    // streaming store: evict-first in L2

        // slot s0 is now free: refill with column w+5 (first used at w+4)
        if (w < Wn - 5) {                          // compile-time (unrolled)
            const int wc = (w + 5) * C2;
            win[0][s0] = __ldg(&row0[wc]);
            win[1][s0] = __ldg(&row1[wc]);
            win[2][s0] = __ldg(&row2[wc]);
        } else if (w == Wn - 5) {
            // phantom col 56 (right edge) must read as zero at w = 55
            win[0][s0] = Z; win[1][s0] = Z; win[2][s0] = Z;
        }
    }
}

extern "C" void kernel_launch(void* const* d_in, const int* in_sizes, int n_in,
                              void* d_out, int out_size)
{
    const float2* x = (const float2*)d_in[0];   // [32,56,56,256] fp32
    const float2* k = (const float2*)d_in[1];   // [3,3,256] fp32
    float2* out = (float2*)d_out;

    dim3 block(C2, 2);          // 256 threads: two full rows per block
    dim3 grid(Bn * Hn / 2);     // 896 blocks
    contour_integration_kernel<<<grid, block>>>(x, k, out);
}